// round 2
// baseline (speedup 1.0000x reference)
#include <cuda_runtime.h>
#include <cstdint>
#include <math.h>

#define BATCH 16
#define CH    256
#define HW    96
#define PIX   (HW*HW)   // 9216

// scratch for z (B,C,H,W) fp32 = 144 MB
__device__ float g_z[(size_t)BATCH * CH * PIX];

// ---------------------------------------------------------------------------
// Stage 1: z = 3*y + w_fea*w_edge + DoG(y),  y = skip + dec
// One block per (b,c) plane. Whole plane + pyramids in shared memory.
// ---------------------------------------------------------------------------
template <int N>
__device__ __forceinline__ float up_sample(const float* __restrict__ d, int i, int j) {
    const float scale = (float)N / 96.0f;
    float fy = (i + 0.5f) * scale - 0.5f;
    float fx = (j + 0.5f) * scale - 0.5f;
    int y0 = (int)floorf(fy); float wy = fy - (float)y0;
    int x0 = (int)floorf(fx); float wx = fx - (float)x0;
    int y0c = max(y0, 0), y1c = min(y0 + 1, N - 1);
    int x0c = max(x0, 0), x1c = min(x0 + 1, N - 1);
    float v00 = d[y0c * N + x0c];
    float v01 = d[y0c * N + x1c];
    float v10 = d[y1c * N + x0c];
    float v11 = d[y1c * N + x1c];
    float v0 = v00 + wx * (v01 - v00);
    float v1 = v10 + wx * (v11 - v10);
    return v0 + wy * (v1 - v0);
}

__global__ void __launch_bounds__(256) stage1_kernel(
    const float* __restrict__ skip, const float* __restrict__ dec,
    const float* __restrict__ w_fea, const float* __restrict__ s1raw,
    const float* __restrict__ s2raw)
{
    extern __shared__ float sm[];
    float* sy = sm;                 // 96*96 = 9216
    float* d0 = sy + PIX;           // 24*24 = 576
    float* d1 = d0 + 576;           // 48*48 = 2304
    float* d2 = d1 + 2304;          // 72*72 = 5184

    int plane = blockIdx.x;         // b*256 + c
    int c = plane & (CH - 1);
    const float* sp = skip + (size_t)plane * PIX;
    const float* dp = dec  + (size_t)plane * PIX;
    float* zp = g_z + (size_t)plane * PIX;
    int tid = threadIdx.x;

    for (int i = tid; i < PIX; i += 256) sy[i] = sp[i] + dp[i];
    __syncthreads();

    // downsample 96 -> 24 : src = 4i+1.5 -> avg of (4i+1, 4i+2)
    for (int idx = tid; idx < 24 * 24; idx += 256) {
        int oi = idx / 24, oj = idx % 24;
        const float* r0 = sy + (4 * oi + 1) * 96 + 4 * oj + 1;
        d0[idx] = 0.25f * (r0[0] + r0[1] + r0[96] + r0[97]);
    }
    // downsample 96 -> 48 : src = 2i+0.5 -> avg of (2i, 2i+1)
    for (int idx = tid; idx < 48 * 48; idx += 256) {
        int oi = idx / 48, oj = idx % 48;
        const float* r0 = sy + (2 * oi) * 96 + 2 * oj;
        d1[idx] = 0.25f * (r0[0] + r0[1] + r0[96] + r0[97]);
    }
    // downsample 96 -> 72 : src = (i+0.5)*4/3 - 0.5 (always interior)
    for (int idx = tid; idx < 72 * 72; idx += 256) {
        int oi = idx / 72, oj = idx % 72;
        float fy = (oi + 0.5f) * (96.0f / 72.0f) - 0.5f;
        float fx = (oj + 0.5f) * (96.0f / 72.0f) - 0.5f;
        int y0 = (int)floorf(fy); float wy = fy - (float)y0;
        int x0 = (int)floorf(fx); float wx = fx - (float)x0;
        const float* r0 = sy + y0 * 96 + x0;
        float v00 = r0[0], v01 = r0[1], v10 = r0[96], v11 = r0[97];
        float v0 = v00 + wx * (v01 - v00);
        float v1 = v10 + wx * (v11 - v10);
        d2[idx] = v0 + wy * (v1 - v0);
    }
    __syncthreads();

    // per-channel DoG kernel coefficients: sigma = 2*sigmoid(raw)
    float sg1 = 2.0f / (1.0f + expf(-s1raw[c]));
    float sg2 = 2.0f / (1.0f + expf(-s2raw[c]));
    float a1 = expf(-0.5f / (sg1 * sg1));
    float a2 = a1 * a1;
    float b1 = expf(-0.5f / (sg2 * sg2));
    float b2 = b1 * b1;
    float in1 = 1.0f / (1.0f + 4.0f * a1 + 4.0f * a2);
    float in2 = 1.0f / (1.0f + 4.0f * b1 + 4.0f * b2);
    float kc = in1 - in2;          // center
    float ke = a1 * in1 - b1 * in2; // edge (r2=1)
    float kq = a2 * in1 - b2 * in2; // corner (r2=2)
    float wf = w_fea[c];

    for (int idx = tid; idx < PIX; idx += 256) {
        int i = idx / 96, j = idx % 96;
        float yv = sy[idx];
        float u0 = up_sample<24>(d0, i, j);
        float u1 = up_sample<48>(d1, i, j);
        float u2 = up_sample<72>(d2, i, j);
        float e0 = fabsf(yv - u0), e1 = fabsf(yv - u1), e2 = fabsf(yv - u2);
        float we = (fabsf(e0 - e1) + fabsf(e0 - e2) + fabsf(e1 - e2)) * (1.0f / 3.0f);
        // 3x3 depthwise DoG with zero padding
        bool up = i > 0, dn = i < 95, lf = j > 0, rt = j < 95;
        float se = 0.0f, sq = 0.0f;
        if (up) se += sy[idx - 96];
        if (dn) se += sy[idx + 96];
        if (lf) se += sy[idx - 1];
        if (rt) se += sy[idx + 1];
        if (up && lf) sq += sy[idx - 97];
        if (up && rt) sq += sy[idx - 95];
        if (dn && lf) sq += sy[idx + 95];
        if (dn && rt) sq += sy[idx + 97];
        float dog = kc * yv + ke * se + kq * sq;
        zp[idx] = 3.0f * yv + wf * we + dog;
    }
}

// ---------------------------------------------------------------------------
// Stage 2: out[b,co,p] = sum_c W[co,c] * z[b,c,p] + skip[b,co,p]
// tf32 mma.sync GEMM. Block tile 128(co) x 128(p), BK=16, double-buffered smem.
// ---------------------------------------------------------------------------
#define GBM 128
#define GBN 128
#define GBK 16
#define ASTR 20    // 128 rows x (16+4) pad -> conflict-free A frag reads
#define BSTR 132   // 16 rows x (128+4) pad

__device__ __forceinline__ uint32_t f2tf32(float x) {
    uint32_t r;
    asm("cvt.rna.tf32.f32 %0, %1;" : "=r"(r) : "f"(x));
    return r;
}
__device__ __forceinline__ void mma_tf32(float* c, const uint32_t* a, const uint32_t* b) {
    asm volatile(
        "mma.sync.aligned.m16n8k8.row.col.f32.tf32.tf32.f32 "
        "{%0,%1,%2,%3}, {%4,%5,%6,%7}, {%8,%9}, {%0,%1,%2,%3};\n"
        : "+f"(c[0]), "+f"(c[1]), "+f"(c[2]), "+f"(c[3])
        : "r"(a[0]), "r"(a[1]), "r"(a[2]), "r"(a[3]), "r"(b[0]), "r"(b[1]));
}

__global__ void __launch_bounds__(256, 2) mixer_gemm(
    const float* __restrict__ Wm, const float* __restrict__ skip,
    float* __restrict__ out)
{
    __shared__ uint32_t As[2][GBM][ASTR];
    __shared__ uint32_t Bs[2][GBK][BSTR];

    int pt = blockIdx.x * GBN;      // pixel tile offset
    int ct = blockIdx.y * GBM;      // out-channel tile offset
    int b  = blockIdx.z;
    const float* Zb = g_z + (size_t)b * CH * PIX;

    int tid  = threadIdx.x;
    int warp = tid >> 5, lane = tid & 31;
    int wm = warp >> 1, wn = warp & 1;     // 4x2 warp grid, warp tile 32x64
    int g = lane >> 2, tig = lane & 3;

    float acc[2][8][4];
#pragma unroll
    for (int t = 0; t < 2; t++)
#pragma unroll
        for (int s = 0; s < 8; s++)
#pragma unroll
            for (int q = 0; q < 4; q++) acc[t][s][q] = 0.0f;

    // global load mapping
    int arow = tid >> 2;            // 0..63 (rows arow, arow+64)
    int akq  = (tid & 3) * 4;       // k offset 0/4/8/12
    int brow = tid >> 5;            // 0..7 (rows brow, brow+8)
    int bcq  = (tid & 31) * 4;      // col offset

    float4 astg0, astg1, bstg0, bstg1;

    // prologue: load + store k-tile 0
    astg0 = *(const float4*)(Wm + (size_t)(ct + arow) * 256 + akq);
    astg1 = *(const float4*)(Wm + (size_t)(ct + arow + 64) * 256 + akq);
    bstg0 = *(const float4*)(Zb + (size_t)brow * PIX + pt + bcq);
    bstg1 = *(const float4*)(Zb + (size_t)(brow + 8) * PIX + pt + bcq);
    {
        As[0][arow][akq + 0] = f2tf32(astg0.x); As[0][arow][akq + 1] = f2tf32(astg0.y);
        As[0][arow][akq + 2] = f2tf32(astg0.z); As[0][arow][akq + 3] = f2tf32(astg0.w);
        As[0][arow + 64][akq + 0] = f2tf32(astg1.x); As[0][arow + 64][akq + 1] = f2tf32(astg1.y);
        As[0][arow + 64][akq + 2] = f2tf32(astg1.z); As[0][arow + 64][akq + 3] = f2tf32(astg1.w);
        Bs[0][brow][bcq + 0] = f2tf32(bstg0.x); Bs[0][brow][bcq + 1] = f2tf32(bstg0.y);
        Bs[0][brow][bcq + 2] = f2tf32(bstg0.z); Bs[0][brow][bcq + 3] = f2tf32(bstg0.w);
        Bs[0][brow + 8][bcq + 0] = f2tf32(bstg1.x); Bs[0][brow + 8][bcq + 1] = f2tf32(bstg1.y);
        Bs[0][brow + 8][bcq + 2] = f2tf32(bstg1.z); Bs[0][brow + 8][bcq + 3] = f2tf32(bstg1.w);
    }
    __syncthreads();

    for (int kt = 0; kt < 16; ++kt) {
        int cur = kt & 1;
        if (kt < 15) {
            int k0 = (kt + 1) * GBK;
            astg0 = *(const float4*)(Wm + (size_t)(ct + arow) * 256 + k0 + akq);
            astg1 = *(const float4*)(Wm + (size_t)(ct + arow + 64) * 256 + k0 + akq);
            bstg0 = *(const float4*)(Zb + (size_t)(k0 + brow) * PIX + pt + bcq);
            bstg1 = *(const float4*)(Zb + (size_t)(k0 + brow + 8) * PIX + pt + bcq);
        }
#pragma unroll
        for (int kk = 0; kk < 2; kk++) {
            uint32_t af[2][4];
#pragma unroll
            for (int t = 0; t < 2; t++) {
                int r = wm * 32 + t * 16;
                af[t][0] = As[cur][r + g][kk * 8 + tig];
                af[t][1] = As[cur][r + g + 8][kk * 8 + tig];
                af[t][2] = As[cur][r + g][kk * 8 + tig + 4];
                af[t][3] = As[cur][r + g + 8][kk * 8 + tig + 4];
            }
            uint32_t bf[8][2];
#pragma unroll
            for (int s = 0; s < 8; s++) {
                int cn = wn * 64 + s * 8 + g;
                bf[s][0] = Bs[cur][kk * 8 + tig][cn];
                bf[s][1] = Bs[cur][kk * 8 + tig + 4][cn];
            }
#pragma unroll
            for (int t = 0; t < 2; t++)
#pragma unroll
                for (int s = 0; s < 8; s++)
                    mma_tf32(acc[t][s], af[t], bf[s]);
        }
        if (kt < 15) {
            int nxt = (kt + 1) & 1;
            As[nxt][arow][akq + 0] = f2tf32(astg0.x); As[nxt][arow][akq + 1] = f2tf32(astg0.y);
            As[nxt][arow][akq + 2] = f2tf32(astg0.z); As[nxt][arow][akq + 3] = f2tf32(astg0.w);
            As[nxt][arow + 64][akq + 0] = f2tf32(astg1.x); As[nxt][arow + 64][akq + 1] = f2tf32(astg1.y);
            As[nxt][arow + 64][akq + 2] = f2tf32(astg1.z); As[nxt][arow + 64][akq + 3] = f2tf32(astg1.w);
            Bs[nxt][brow][bcq + 0] = f2tf32(bstg0.x); Bs[nxt][brow][bcq + 1] = f2tf32(bstg0.y);
            Bs[nxt][brow][bcq + 2] = f2tf32(bstg0.z); Bs[nxt][brow][bcq + 3] = f2tf32(bstg0.w);
            Bs[nxt][brow + 8][bcq + 0] = f2tf32(bstg1.x); Bs[nxt][brow + 8][bcq + 1] = f2tf32(bstg1.y);
            Bs[nxt][brow + 8][bcq + 2] = f2tf32(bstg1.z); Bs[nxt][brow + 8][bcq + 3] = f2tf32(bstg1.w);
        }
        __syncthreads();
    }

    // epilogue: + skip, write out (float2 stores)
#pragma unroll
    for (int t = 0; t < 2; t++) {
        int row = ct + wm * 32 + t * 16 + g;
#pragma unroll
        for (int s = 0; s < 8; s++) {
            int col = pt + wn * 64 + s * 8 + tig * 2;
            size_t base0 = ((size_t)b * CH + row) * PIX + col;
            size_t base1 = base0 + (size_t)8 * PIX;
            float2 k0 = *(const float2*)(skip + base0);
            float2 k1 = *(const float2*)(skip + base1);
            float2 o0 = make_float2(acc[t][s][0] + k0.x, acc[t][s][1] + k0.y);
            float2 o1 = make_float2(acc[t][s][2] + k1.x, acc[t][s][3] + k1.y);
            *(float2*)(out + base0) = o0;
            *(float2*)(out + base1) = o1;
        }
    }
}

// ---------------------------------------------------------------------------
extern "C" void kernel_launch(void* const* d_in, const int* in_sizes, int n_in,
                              void* d_out, int out_size) {
    const float* skip  = (const float*)d_in[0];
    const float* dec   = (const float*)d_in[1];
    const float* wfea  = (const float*)d_in[2];
    const float* s1    = (const float*)d_in[3];
    const float* s2    = (const float*)d_in[4];
    const float* mixw  = (const float*)d_in[5];
    float* out = (float*)d_out;

    int smem1 = (PIX + 576 + 2304 + 5184) * (int)sizeof(float);  // 69120 B
    cudaFuncSetAttribute(stage1_kernel, cudaFuncAttributeMaxDynamicSharedMemorySize, smem1);
    stage1_kernel<<<BATCH * CH, 256, smem1>>>(skip, dec, wfea, s1, s2);

    dim3 g2(PIX / GBN, CH / GBM, BATCH);
    mixer_gemm<<<g2, 256>>>(mixw, skip, out);
}

// round 5
// speedup vs baseline: 1.1685x; 1.1685x over previous
#include <cuda_runtime.h>
#include <cstdint>
#include <math.h>

#define BATCH 16
#define CH    256
#define HW    96
#define PIX   (HW*HW)   // 9216
#define PSTR  100       // padded row stride for sy (98 rows x 100)

// scratch: z (tf32-rounded fp32 bits) + pre-transposed/converted weights
__device__ float g_z[(size_t)BATCH * CH * PIX];
__device__ float g_At[CH * CH];    // At[ci][co] = tf32(W[co][ci])

__device__ __forceinline__ uint32_t f2tf32(float x) {
    uint32_t r;
    asm("cvt.rna.tf32.f32 %0, %1;" : "=r"(r) : "f"(x));
    return r;
}

// ---------------------------------------------------------------------------
// prep: transpose + tf32-round mixer weight (256x256)
// ---------------------------------------------------------------------------
__global__ void prep_w(const float* __restrict__ W) {
    int t = blockIdx.x * 256 + threadIdx.x;   // t = co*256+ci
    int co = t >> 8, ci = t & 255;
    g_At[ci * 256 + co] = __uint_as_float(f2tf32(W[t]));
}

// ---------------------------------------------------------------------------
// Stage 1: z = 3y + w_fea*w_edge + DoG(y),  y = skip + dec   (one CTA / plane)
// 192 threads: thread = (r = tid/96, j = tid%96); iterates rows i = 2*it + r.
// sy is zero-padded (98 x 100) -> branchless 3x3 DoG.
// z written tf32-rounded so stage2 can cp.async it directly.
// ---------------------------------------------------------------------------
__global__ void __launch_bounds__(192) stage1_kernel(
    const float* __restrict__ skip, const float* __restrict__ dec,
    const float* __restrict__ w_fea, const float* __restrict__ s1raw,
    const float* __restrict__ s2raw)
{
    extern __shared__ float sm[];
    float* syp = sm;                  // 98*100 = 9800
    float* d0  = syp + 9800;          // 24*24  = 576
    float* d1  = d0 + 576;            // 48*48  = 2304
    float* d2  = d1 + 2304;           // 72*72  = 5184   total 17864 floats

    int plane = blockIdx.x;
    int c = plane & (CH - 1);
    const float* sp = skip + (size_t)plane * PIX;
    const float* dp = dec  + (size_t)plane * PIX;
    float* zp = g_z + (size_t)plane * PIX;
    int tid = threadIdx.x;

    // zero border of padded plane
    for (int x = tid; x < PSTR; x += 192) { syp[x] = 0.0f; syp[97 * PSTR + x] = 0.0f; }
    for (int r = tid; r < 98; r += 192)   { syp[r * PSTR] = 0.0f; syp[r * PSTR + 97] = 0.0f; }
    __syncthreads();

    // y = skip + dec, vectorized load, scalar padded store
    {
        const float4* s4 = (const float4*)sp;
        const float4* d4 = (const float4*)dp;
        for (int q = tid; q < PIX / 4; q += 192) {
            float4 a = s4[q], b = d4[q];
            int i = q / 24;               // q*4/96
            int j = (q % 24) * 4;
            float* dst = syp + (i + 1) * PSTR + (j + 1);
            dst[0] = a.x + b.x; dst[1] = a.y + b.y;
            dst[2] = a.z + b.z; dst[3] = a.w + b.w;
        }
    }
    __syncthreads();

#define SY(i, j) syp[((i) + 1) * PSTR + ((j) + 1)]
    // downsample 96 -> 24 : avg of (4i+1,4i+2)x(4j+1,4j+2)
    for (int e = tid; e < 24 * 24; e += 192) {
        int oi = e / 24, oj = e % 24;
        d0[e] = 0.25f * (SY(4 * oi + 1, 4 * oj + 1) + SY(4 * oi + 1, 4 * oj + 2) +
                         SY(4 * oi + 2, 4 * oj + 1) + SY(4 * oi + 2, 4 * oj + 2));
    }
    // downsample 96 -> 48
    for (int e = tid; e < 48 * 48; e += 192) {
        int oi = e / 48, oj = e % 48;
        d1[e] = 0.25f * (SY(2 * oi, 2 * oj) + SY(2 * oi, 2 * oj + 1) +
                         SY(2 * oi + 1, 2 * oj) + SY(2 * oi + 1, 2 * oj + 1));
    }
    // downsample 96 -> 72 (bilinear, always interior)
    for (int e = tid; e < 72 * 72; e += 192) {
        int oi = e / 72, oj = e % 72;
        float fy = fmaf((float)oi, 96.0f / 72.0f, 96.0f / 144.0f - 0.5f);
        float fx = fmaf((float)oj, 96.0f / 72.0f, 96.0f / 144.0f - 0.5f);
        int y0 = (int)floorf(fy); float wy = fy - (float)y0;
        int x0 = (int)floorf(fx); float wx = fx - (float)x0;
        const float* r0 = &SY(y0, x0);
        float v00 = r0[0], v01 = r0[1], v10 = r0[PSTR], v11 = r0[PSTR + 1];
        float h0 = fmaf(wx, v01 - v00, v00);
        float h1 = fmaf(wx, v11 - v10, v10);
        d2[e] = fmaf(wy, h1 - h0, h0);
    }
    __syncthreads();

    // per-channel DoG kernel coefficients
    float sg1 = 2.0f / (1.0f + expf(-s1raw[c]));
    float sg2 = 2.0f / (1.0f + expf(-s2raw[c]));
    float a1 = expf(-0.5f / (sg1 * sg1)), a2 = a1 * a1;
    float b1 = expf(-0.5f / (sg2 * sg2)), b2 = b1 * b1;
    float in1 = 1.0f / (1.0f + 4.0f * a1 + 4.0f * a2);
    float in2 = 1.0f / (1.0f + 4.0f * b1 + 4.0f * b2);
    float kc3 = 3.0f + in1 - in2;
    float ke = a1 * in1 - b1 * in2;
    float kq = a2 * in1 - b2 * in2;
    float wf = w_fea[c];

    // per-thread x-direction bilinear setup (fixed column j)
    int rhalf = tid / 96;
    int j = tid - rhalf * 96;

    float fx0 = 0.25f * j - 0.375f;
    int xi0 = (int)floorf(fx0); float wx0 = fx0 - (float)xi0;
    int x0a = max(xi0, 0), x0b = min(xi0 + 1, 23);
    float fx1 = 0.5f * j - 0.25f;
    int xi1 = (int)floorf(fx1); float wx1 = fx1 - (float)xi1;
    int x1a = max(xi1, 0), x1b = min(xi1 + 1, 47);
    float fx2 = 0.75f * j - 0.125f;
    int xi2 = (int)floorf(fx2); float wx2 = fx2 - (float)xi2;
    int x2a = max(xi2, 0), x2b = min(xi2 + 1, 71);

#pragma unroll 4
    for (int it = 0; it < 48; ++it) {
        int i = it * 2 + rhalf;

        float fy0 = 0.25f * i - 0.375f;
        int yi0 = (int)floorf(fy0); float wy0 = fy0 - (float)yi0;
        const float* p0a = d0 + max(yi0, 0) * 24;
        const float* p0b = d0 + min(yi0 + 1, 23) * 24;
        float u0;
        { float v00 = p0a[x0a], v01 = p0a[x0b], v10 = p0b[x0a], v11 = p0b[x0b];
          float h0 = fmaf(wx0, v01 - v00, v00);
          float h1 = fmaf(wx0, v11 - v10, v10);
          u0 = fmaf(wy0, h1 - h0, h0); }

        float fy1 = 0.5f * i - 0.25f;
        int yi1 = (int)floorf(fy1); float wy1 = fy1 - (float)yi1;
        const float* p1a = d1 + max(yi1, 0) * 48;
        const float* p1b = d1 + min(yi1 + 1, 47) * 48;
        float u1;
        { float v00 = p1a[x1a], v01 = p1a[x1b], v10 = p1b[x1a], v11 = p1b[x1b];
          float h0 = fmaf(wx1, v01 - v00, v00);
          float h1 = fmaf(wx1, v11 - v10, v10);
          u1 = fmaf(wy1, h1 - h0, h0); }

        float fy2 = 0.75f * i - 0.125f;
        int yi2 = (int)floorf(fy2); float wy2 = fy2 - (float)yi2;
        const float* p2a = d2 + max(yi2, 0) * 72;
        const float* p2b = d2 + min(yi2 + 1, 71) * 72;
        float u2;
        { float v00 = p2a[x2a], v01 = p2a[x2b], v10 = p2b[x2a], v11 = p2b[x2b];
          float h0 = fmaf(wx2, v01 - v00, v00);
          float h1 = fmaf(wx2, v11 - v10, v10);
          u2 = fmaf(wy2, h1 - h0, h0); }

        const float* pc = syp + (i + 1) * PSTR + (j + 1);
        float yv = pc[0];
        float se = pc[-1] + pc[1] + pc[-PSTR] + pc[PSTR];
        float sq = pc[-PSTR - 1] + pc[-PSTR + 1] + pc[PSTR - 1] + pc[PSTR + 1];

        float e0 = fabsf(yv - u0), e1 = fabsf(yv - u1), e2 = fabsf(yv - u2);
        float we = (fabsf(e0 - e1) + fabsf(e0 - e2) + fabsf(e1 - e2)) * (1.0f / 3.0f);
        float z = kc3 * yv + wf * we + ke * se + kq * sq;
        zp[i * 96 + j] = __uint_as_float(f2tf32(z));
    }
#undef SY
}

// ---------------------------------------------------------------------------
// Stage 2: out[b,co,p] = sum_ci W[co,ci]*z[b,ci,p] + skip[b,co,p]
// tf32 mma, block tile 256(co) x 128(p), BK=16, 4-stage cp.async pipeline.
// A and B are pre-rounded tf32 in gmem -> pure async copies, no conversion.
// ---------------------------------------------------------------------------
#define GM 256
#define GN 128
#define GK 16
#define AST 264     // As[k][m], stride 264 (pad 8 -> conflict-free frag loads)
#define BST 136     // Bs[k][n], stride 136
#define NSTAGE 4
#define A_FLOATS (GK * AST)       // 4224
#define B_FLOATS (GK * BST)       // 2176

__device__ __forceinline__ void cp_async16(uint32_t saddr, const void* gptr) {
    asm volatile("cp.async.ca.shared.global [%0], [%1], 16;\n" :: "r"(saddr), "l"(gptr));
}
__device__ __forceinline__ void cp_commit() {
    asm volatile("cp.async.commit_group;\n");
}
template <int N>
__device__ __forceinline__ void cp_wait() {
    asm volatile("cp.async.wait_group %0;\n" :: "n"(N));
}
__device__ __forceinline__ void mma_tf32(float* c, const uint32_t* a, const uint32_t* b) {
    asm volatile(
        "mma.sync.aligned.m16n8k8.row.col.f32.tf32.tf32.f32 "
        "{%0,%1,%2,%3}, {%4,%5,%6,%7}, {%8,%9}, {%0,%1,%2,%3};\n"
        : "+f"(c[0]), "+f"(c[1]), "+f"(c[2]), "+f"(c[3])
        : "r"(a[0]), "r"(a[1]), "r"(a[2]), "r"(a[3]), "r"(b[0]), "r"(b[1]));
}

__global__ void __launch_bounds__(512, 1) mixer_gemm(
    const float* __restrict__ skip, float* __restrict__ out)
{
    extern __shared__ float sm2[];
    float* As = sm2;                          // NSTAGE * A_FLOATS
    float* Bs = sm2 + NSTAGE * A_FLOATS;      // NSTAGE * B_FLOATS

    int pt = blockIdx.x * GN;
    int b  = blockIdx.y;
    const float* Zb = g_z + (size_t)b * CH * PIX;

    int tid  = threadIdx.x;
    int warp = tid >> 5, lane = tid & 31;
    int wm = warp >> 1, wn = warp & 1;        // 8x2 warps, warp tile 32x64
    int g = lane >> 2, tig = lane & 3;

    // cp.async source/dest mapping (uniform per thread)
    int ac0 = tid * 8;                        // first A chunk float offset (2 chunks/thread)
    int ak0 = ac0 >> 8,  am0 = ac0 & 255;
    int ac1 = ac0 + 4;
    int ak1 = ac1 >> 8,  am1 = ac1 & 255;
    int bo  = tid * 4;
    int bk  = bo >> 7,   bn = bo & 127;

    float acc[2][8][4];
#pragma unroll
    for (int t = 0; t < 2; t++)
#pragma unroll
        for (int s = 0; s < 8; s++)
#pragma unroll
            for (int q = 0; q < 4; q++) acc[t][s][q] = 0.0f;

    // prologue: issue stages 0..2
#pragma unroll
    for (int st = 0; st < NSTAGE - 1; ++st) {
        const float* asrc = g_At + st * GK * 256;
        float* abase = As + st * A_FLOATS;
        cp_async16((uint32_t)__cvta_generic_to_shared(abase + ak0 * AST + am0), asrc + ac0);
        cp_async16((uint32_t)__cvta_generic_to_shared(abase + ak1 * AST + am1), asrc + ac1);
        const float* bsrc = Zb + (size_t)(st * GK + bk) * PIX + pt + bn;
        float* bbase = Bs + st * B_FLOATS;
        cp_async16((uint32_t)__cvta_generic_to_shared(bbase + bk * BST + bn), bsrc);
        cp_commit();
    }

    for (int kt = 0; kt < 16; ++kt) {
        cp_wait<NSTAGE - 2>();
        __syncthreads();

        int nk = kt + NSTAGE - 1;
        if (nk < 16) {
            int st = nk & (NSTAGE - 1);
            const float* asrc = g_At + nk * GK * 256;
            float* abase = As + st * A_FLOATS;
            cp_async16((uint32_t)__cvta_generic_to_shared(abase + ak0 * AST + am0), asrc + ac0);
            cp_async16((uint32_t)__cvta_generic_to_shared(abase + ak1 * AST + am1), asrc + ac1);
            const float* bsrc = Zb + (size_t)(nk * GK + bk) * PIX + pt + bn;
            float* bbase = Bs + st * B_FLOATS;
            cp_async16((uint32_t)__cvta_generic_to_shared(bbase + bk * BST + bn), bsrc);
        }
        cp_commit();

        const float* as_s = As + (kt & (NSTAGE - 1)) * A_FLOATS;
        const float* bs_s = Bs + (kt & (NSTAGE - 1)) * B_FLOATS;
#pragma unroll
        for (int kk = 0; kk < 2; kk++) {
            const uint32_t* ar0 = (const uint32_t*)(as_s + (kk * 8 + tig) * AST);
            const uint32_t* ar1 = (const uint32_t*)(as_s + (kk * 8 + tig + 4) * AST);
            uint32_t af[2][4];
#pragma unroll
            for (int t = 0; t < 2; t++) {
                int m0 = wm * 32 + t * 16 + g;
                af[t][0] = ar0[m0];
                af[t][1] = ar0[m0 + 8];
                af[t][2] = ar1[m0];
                af[t][3] = ar1[m0 + 8];
            }
            const uint32_t* br0 = (const uint32_t*)(bs_s + (kk * 8 + tig) * BST);
            const uint32_t* br1 = (const uint32_t*)(bs_s + (kk * 8 + tig + 4) * BST);
            uint32_t bf[8][2];
#pragma unroll
            for (int s = 0; s < 8; s++) {
                int cn = wn * 64 + s * 8 + g;
                bf[s][0] = br0[cn];
                bf[s][1] = br1[cn];
            }
#pragma unroll
            for (int t = 0; t < 2; t++)
#pragma unroll
                for (int s = 0; s < 8; s++)
                    mma_tf32(acc[t][s], af[t], bf[s]);
        }
        __syncthreads();
    }

    // epilogue: + skip, write out
#pragma unroll
    for (int t = 0; t < 2; t++) {
        int row = wm * 32 + t * 16 + g;
#pragma unroll
        for (int s = 0; s < 8; s++) {
            int col = pt + wn * 64 + s * 8 + tig * 2;
            size_t base0 = ((size_t)b * CH + row) * PIX + col;
            size_t base1 = base0 + (size_t)8 * PIX;
            float2 k0 = *(const float2*)(skip + base0);
            float2 k1 = *(const float2*)(skip + base1);
            float2 o0 = make_float2(acc[t][s][0] + k0.x, acc[t][s][1] + k0.y);
            float2 o1 = make_float2(acc[t][s][2] + k1.x, acc[t][s][3] + k1.y);
            *(float2*)(out + base0) = o0;
            *(float2*)(out + base1) = o1;
        }
    }
}

// ---------------------------------------------------------------------------
extern "C" void kernel_launch(void* const* d_in, const int* in_sizes, int n_in,
                              void* d_out, int out_size) {
    const float* skip = (const float*)d_in[0];
    const float* dec  = (const float*)d_in[1];
    const float* wfea = (const float*)d_in[2];
    const float* s1   = (const float*)d_in[3];
    const float* s2   = (const float*)d_in[4];
    const float* mixw = (const float*)d_in[5];
    float* out = (float*)d_out;

    prep_w<<<256, 256>>>(mixw);

    int smem1 = 17864 * (int)sizeof(float);   // 71456 B
    static bool attr_done = false;
    cudaFuncSetAttribute(stage1_kernel, cudaFuncAttributeMaxDynamicSharedMemorySize, smem1);
    stage1_kernel<<<BATCH * CH, 192, smem1>>>(skip, dec, wfea, s1, s2);

    int smem2 = NSTAGE * (A_FLOATS + B_FLOATS) * (int)sizeof(float);  // 102400 B
    cudaFuncSetAttribute(mixer_gemm, cudaFuncAttributeMaxDynamicSharedMemorySize, smem2);
    dim3 g2(PIX / GN, BATCH, 1);
    mixer_gemm<<<g2, 512, smem2>>>(skip, out);
    (void)attr_done;
}

// round 7
// speedup vs baseline: 1.2813x; 1.0966x over previous
#include <cuda_runtime.h>
#include <cstdint>
#include <math.h>

#define BATCH 16
#define CH    256
#define HW    96
#define PIX   (HW*HW)   // 9216
#define PSTR  104       // padded row stride for sy (98 rows x 104), col offset 4

// scratch: z (tf32-rounded fp32 bits) + fragment-order tf32 weights
__device__ float g_z[(size_t)BATCH * CH * PIX];
__device__ float g_Asw[CH * CH];   // mma-fragment-ordered tf32(W)

__device__ __forceinline__ uint32_t f2tf32(float x) {
    uint32_t r;
    asm("cvt.rna.tf32.f32 %0, %1;" : "=r"(r) : "f"(x));
    return r;
}

// ---------------------------------------------------------------------------
// Stage 1: z = 3y + w_fea*w_edge + DoG(y),  y = skip + dec   (one CTA / plane)
// 384 threads: thread = (r = tid/96 in 0..3, j = tid%96); rows i = 4*it + r.
// sy zero-padded (98 x 104, interior at col 4) -> branchless DoG, STS.128 fill.
// Also folds in the weight pre-swizzle (blocks 0..255, threads 0..255):
// g_Asw layout [kt16][kk2][wm8][t2][lane32][q4] matches the GEMM's A fragment
// register order exactly, so the GEMM loads A with single LDS.128s.
// ---------------------------------------------------------------------------
__global__ void __launch_bounds__(384) stage1_kernel(
    const float* __restrict__ skip, const float* __restrict__ dec,
    const float* __restrict__ w_fea, const float* __restrict__ s1raw,
    const float* __restrict__ s2raw, const float* __restrict__ W)
{
    extern __shared__ float sm[];
    float* syp = sm;                  // 98*104 = 10192
    float* d0  = syp + 10192;         // 24*24  = 576
    float* d1  = d0 + 576;            // 48*48  = 2304
    float* d2  = d1 + 2304;           // 72*72  = 5184   total 18256 floats

    int plane = blockIdx.x;
    int c = plane & (CH - 1);
    const float* sp = skip + (size_t)plane * PIX;
    const float* dp = dec  + (size_t)plane * PIX;
    float* zp = g_z + (size_t)plane * PIX;
    int tid = threadIdx.x;

    // fold-in: weight fragment swizzle (independent of the rest of this kernel)
    if (blockIdx.x < 256 && tid < 256) {
        int o = blockIdx.x * 256 + tid;
        int q    = o & 3;
        int lane = (o >> 2) & 31;
        int t    = (o >> 7) & 1;
        int wm   = (o >> 8) & 7;
        int kk   = (o >> 11) & 1;
        int kt   = o >> 12;
        int g = lane >> 2, tig = lane & 3;
        int co = wm * 32 + t * 16 + g + (q & 1) * 8;
        int ci = kt * 16 + kk * 8 + tig + (q >> 1) * 4;
        g_Asw[o] = __uint_as_float(f2tf32(W[co * 256 + ci]));
    }

    // zero border of padded plane (rows 0,97 full; cols 3,100 each row)
    for (int x = tid; x < PSTR; x += 384) { syp[x] = 0.0f; syp[97 * PSTR + x] = 0.0f; }
    for (int r = tid; r < 98; r += 384)   { syp[r * PSTR + 3] = 0.0f; syp[r * PSTR + 100] = 0.0f; }
    __syncthreads();

    // y = skip + dec, float4 load + aligned float4 padded store
    {
        const float4* s4 = (const float4*)sp;
        const float4* d4 = (const float4*)dp;
        for (int q = tid; q < PIX / 4; q += 384) {
            float4 a = s4[q], b = d4[q];
            int i = q / 24;
            int j4 = (q - i * 24) * 4;
            float4 v = make_float4(a.x + b.x, a.y + b.y, a.z + b.z, a.w + b.w);
            *(float4*)(syp + (i + 1) * PSTR + 4 + j4) = v;
        }
    }
    __syncthreads();

#define SY(i, j) syp[((i) + 1) * PSTR + ((j) + 4)]
    // downsample 96 -> 24 : avg of (4i+1,4i+2)x(4j+1,4j+2)
    for (int e = tid; e < 24 * 24; e += 384) {
        int oi = e / 24, oj = e % 24;
        d0[e] = 0.25f * (SY(4 * oi + 1, 4 * oj + 1) + SY(4 * oi + 1, 4 * oj + 2) +
                         SY(4 * oi + 2, 4 * oj + 1) + SY(4 * oi + 2, 4 * oj + 2));
    }
    // downsample 96 -> 48
    for (int e = tid; e < 48 * 48; e += 384) {
        int oi = e / 48, oj = e % 48;
        d1[e] = 0.25f * (SY(2 * oi, 2 * oj) + SY(2 * oi, 2 * oj + 1) +
                         SY(2 * oi + 1, 2 * oj) + SY(2 * oi + 1, 2 * oj + 1));
    }
    // downsample 96 -> 72 (bilinear, always interior)
    for (int e = tid; e < 72 * 72; e += 384) {
        int oi = e / 72, oj = e % 72;
        float fy = fmaf((float)oi, 96.0f / 72.0f, 96.0f / 144.0f - 0.5f);
        float fx = fmaf((float)oj, 96.0f / 72.0f, 96.0f / 144.0f - 0.5f);
        int y0 = (int)floorf(fy); float wy = fy - (float)y0;
        int x0 = (int)floorf(fx); float wx = fx - (float)x0;
        const float* r0 = &SY(y0, x0);
        float v00 = r0[0], v01 = r0[1], v10 = r0[PSTR], v11 = r0[PSTR + 1];
        float h0 = fmaf(wx, v01 - v00, v00);
        float h1 = fmaf(wx, v11 - v10, v10);
        d2[e] = fmaf(wy, h1 - h0, h0);
    }
    __syncthreads();

    // per-channel DoG kernel coefficients
    float sg1 = 2.0f / (1.0f + expf(-s1raw[c]));
    float sg2 = 2.0f / (1.0f + expf(-s2raw[c]));
    float a1 = expf(-0.5f / (sg1 * sg1)), a2 = a1 * a1;
    float b1 = expf(-0.5f / (sg2 * sg2)), b2 = b1 * b1;
    float in1 = 1.0f / (1.0f + 4.0f * a1 + 4.0f * a2);
    float in2 = 1.0f / (1.0f + 4.0f * b1 + 4.0f * b2);
    float kc3 = 3.0f + in1 - in2;
    float ke = a1 * in1 - b1 * in2;
    float kq = a2 * in1 - b2 * in2;
    float wf = w_fea[c];

    // per-thread x-direction bilinear setup (fixed column j)
    int r = tid / 96;
    int j = tid - r * 96;

    float fx0 = 0.25f * j - 0.375f;
    int xi0 = (int)floorf(fx0); float wx0 = fx0 - (float)xi0;
    int x0a = max(xi0, 0), x0b = min(xi0 + 1, 23);
    float fx1 = 0.5f * j - 0.25f;
    int xi1 = (int)floorf(fx1); float wx1 = fx1 - (float)xi1;
    int x1a = max(xi1, 0), x1b = min(xi1 + 1, 47);
    float fx2 = 0.75f * j - 0.125f;
    int xi2 = (int)floorf(fx2); float wx2 = fx2 - (float)xi2;
    int x2a = max(xi2, 0), x2b = min(xi2 + 1, 71);

#pragma unroll 4
    for (int it = 0; it < 24; ++it) {
        int i = it * 4 + r;

        float fy0 = 0.25f * i - 0.375f;
        int yi0 = (int)floorf(fy0); float wy0 = fy0 - (float)yi0;
        const float* p0a = d0 + max(yi0, 0) * 24;
        const float* p0b = d0 + min(yi0 + 1, 23) * 24;
        float u0;
        { float v00 = p0a[x0a], v01 = p0a[x0b], v10 = p0b[x0a], v11 = p0b[x0b];
          float h0 = fmaf(wx0, v01 - v00, v00);
          float h1 = fmaf(wx0, v11 - v10, v10);
          u0 = fmaf(wy0, h1 - h0, h0); }

        float fy1 = 0.5f * i - 0.25f;
        int yi1 = (int)floorf(fy1); float wy1 = fy1 - (float)yi1;
        const float* p1a = d1 + max(yi1, 0) * 48;
        const float* p1b = d1 + min(yi1 + 1, 47) * 48;
        float u1;
        { float v00 = p1a[x1a], v01 = p1a[x1b], v10 = p1b[x1a], v11 = p1b[x1b];
          float h0 = fmaf(wx1, v01 - v00, v00);
          float h1 = fmaf(wx1, v11 - v10, v10);
          u1 = fmaf(wy1, h1 - h0, h0); }

        float fy2 = 0.75f * i - 0.125f;
        int yi2 = (int)floorf(fy2); float wy2 = fy2 - (float)yi2;
        const float* p2a = d2 + max(yi2, 0) * 72;
        const float* p2b = d2 + min(yi2 + 1, 71) * 72;
        float u2;
        { float v00 = p2a[x2a], v01 = p2a[x2b], v10 = p2b[x2a], v11 = p2b[x2b];
          float h0 = fmaf(wx2, v01 - v00, v00);
          float h1 = fmaf(wx2, v11 - v10, v10);
          u2 = fmaf(wy2, h1 - h0, h0); }

        const float* pc = syp + (i + 1) * PSTR + (j + 4);
        float yv = pc[0];
        float se = pc[-1] + pc[1] + pc[-PSTR] + pc[PSTR];
        float sq = pc[-PSTR - 1] + pc[-PSTR + 1] + pc[PSTR - 1] + pc[PSTR + 1];

        float e0 = fabsf(yv - u0), e1 = fabsf(yv - u1), e2 = fabsf(yv - u2);
        float we = (fabsf(e0 - e1) + fabsf(e0 - e2) + fabsf(e1 - e2)) * (1.0f / 3.0f);
        float z = kc3 * yv + wf * we + ke * se + kq * sq;
        zp[i * 96 + j] = __uint_as_float(f2tf32(z));
    }
#undef SY
}

// ---------------------------------------------------------------------------
// Stage 2: out[b,co,p] = sum_ci W[co,ci]*z[b,ci,p] + skip[b,co,p]
// tf32 mma, block tile 256(co) x 128(p), BK=16, 5-stage cp.async pipeline.
// A is pre-swizzled into fragment order -> one LDS.128 per (kk,t) per thread.
// ---------------------------------------------------------------------------
#define GN 128
#define GK 16
#define BST 136
#define NSTAGE 5
#define A_FLOATS (GK * 256)       // 4096 (fragment order, no padding)
#define B_FLOATS (GK * BST)       // 2176
#define STAGE_FLOATS (A_FLOATS + B_FLOATS)

__device__ __forceinline__ void cp_async16(uint32_t saddr, const void* gptr) {
    asm volatile("cp.async.ca.shared.global [%0], [%1], 16;\n" :: "r"(saddr), "l"(gptr));
}
__device__ __forceinline__ void cp_commit() {
    asm volatile("cp.async.commit_group;\n");
}
template <int N>
__device__ __forceinline__ void cp_wait() {
    asm volatile("cp.async.wait_group %0;\n" :: "n"(N));
}
__device__ __forceinline__ void mma_tf32(float* c, const uint32_t* a, const uint32_t* b) {
    asm volatile(
        "mma.sync.aligned.m16n8k8.row.col.f32.tf32.tf32.f32 "
        "{%0,%1,%2,%3}, {%4,%5,%6,%7}, {%8,%9}, {%0,%1,%2,%3};\n"
        : "+f"(c[0]), "+f"(c[1]), "+f"(c[2]), "+f"(c[3])
        : "r"(a[0]), "r"(a[1]), "r"(a[2]), "r"(a[3]), "r"(b[0]), "r"(b[1]));
}

__global__ void __launch_bounds__(512, 1) mixer_gemm(
    const float* __restrict__ skip, float* __restrict__ out)
{
    extern __shared__ float sm2[];

    int pt = blockIdx.x * GN;
    int b  = blockIdx.y;
    const float* Zb = g_z + (size_t)b * CH * PIX;

    int tid  = threadIdx.x;
    int warp = tid >> 5, lane = tid & 31;
    int wm = warp >> 1, wn = warp & 1;        // 8x2 warps, warp tile 32x64
    int g = lane >> 2, tig = lane & 3;

    // cp.async mappings
    int ao = tid * 8;                         // two 16B A chunks per thread
    int bo = tid * 4;
    int bk = bo >> 7, bn = bo & 127;

    float acc[2][8][4];
#pragma unroll
    for (int t = 0; t < 2; t++)
#pragma unroll
        for (int s = 0; s < 8; s++)
#pragma unroll
            for (int q = 0; q < 4; q++) acc[t][s][q] = 0.0f;

    // prologue: issue stages 0..NSTAGE-2
#pragma unroll
    for (int st = 0; st < NSTAGE - 1; ++st) {
        float* base = sm2 + st * STAGE_FLOATS;
        const float* asrc = g_Asw + st * A_FLOATS;
        cp_async16((uint32_t)__cvta_generic_to_shared(base + ao), asrc + ao);
        cp_async16((uint32_t)__cvta_generic_to_shared(base + ao + 4), asrc + ao + 4);
        const float* bsrc = Zb + (size_t)(st * GK + bk) * PIX + pt + bn;
        cp_async16((uint32_t)__cvta_generic_to_shared(base + A_FLOATS + bk * BST + bn), bsrc);
        cp_commit();
    }

    int cur = 0, nxts = NSTAGE - 1;
    for (int kt = 0; kt < 16; ++kt) {
        cp_wait<NSTAGE - 2>();
        __syncthreads();

        int nk = kt + NSTAGE - 1;
        if (nk < 16) {
            float* base = sm2 + nxts * STAGE_FLOATS;
            const float* asrc = g_Asw + nk * A_FLOATS;
            cp_async16((uint32_t)__cvta_generic_to_shared(base + ao), asrc + ao);
            cp_async16((uint32_t)__cvta_generic_to_shared(base + ao + 4), asrc + ao + 4);
            const float* bsrc = Zb + (size_t)(nk * GK + bk) * PIX + pt + bn;
            cp_async16((uint32_t)__cvta_generic_to_shared(base + A_FLOATS + bk * BST + bn), bsrc);
        }
        cp_commit();

        const float* as_s = sm2 + cur * STAGE_FLOATS;
        const float* bs_s = as_s + A_FLOATS;
#pragma unroll
        for (int kk = 0; kk < 2; kk++) {
            // A fragments: one LDS.128 per t, conflict-free (lane-contiguous)
            uint4 a0 = *(const uint4*)(as_s + (((kk * 8 + wm) * 2 + 0) * 32 + lane) * 4);
            uint4 a1 = *(const uint4*)(as_s + (((kk * 8 + wm) * 2 + 1) * 32 + lane) * 4);
            const uint32_t* br0 = (const uint32_t*)(bs_s + (kk * 8 + tig) * BST);
            const uint32_t* br1 = (const uint32_t*)(bs_s + (kk * 8 + tig + 4) * BST);
            uint32_t bf[8][2];
#pragma unroll
            for (int s = 0; s < 8; s++) {
                int cn = wn * 64 + s * 8 + g;
                bf[s][0] = br0[cn];
                bf[s][1] = br1[cn];
            }
#pragma unroll
            for (int s = 0; s < 8; s++) {
                mma_tf32(acc[0][s], &a0.x, bf[s]);
                mma_tf32(acc[1][s], &a1.x, bf[s]);
            }
        }
        __syncthreads();
        cur = (cur == NSTAGE - 1) ? 0 : cur + 1;
        nxts = (nxts == NSTAGE - 1) ? 0 : nxts + 1;
    }

    // epilogue: + skip, write out
#pragma unroll
    for (int t = 0; t < 2; t++) {
        int row = wm * 32 + t * 16 + g;
#pragma unroll
        for (int s = 0; s < 8; s++) {
            int col = pt + wn * 64 + s * 8 + tig * 2;
            size_t base0 = ((size_t)b * CH + row) * PIX + col;
            size_t base1 = base0 + (size_t)8 * PIX;
            float2 k0 = *(const float2*)(skip + base0);
            float2 k1 = *(const float2*)(skip + base1);
            float2 o0 = make_float2(acc[t][s][0] + k0.x, acc[t][s][1] + k0.y);
            float2 o1 = make_float2(acc[t][s][2] + k1.x, acc[t][s][3] + k1.y);
            *(float2*)(out + base0) = o0;
            *(float2*)(out + base1) = o1;
        }
    }
}

// ---------------------------------------------------------------------------
extern "C" void kernel_launch(void* const* d_in, const int* in_sizes, int n_in,
                              void* d_out, int out_size) {
    const float* skip = (const float*)d_in[0];
    const float* dec  = (const float*)d_in[1];
    const float* wfea = (const float*)d_in[2];
    const float* s1   = (const float*)d_in[3];
    const float* s2   = (const float*)d_in[4];
    const float* mixw = (const float*)d_in[5];
    float* out = (float*)d_out;

    int smem1 = 18256 * (int)sizeof(float);   // 73024 B
    cudaFuncSetAttribute(stage1_kernel, cudaFuncAttributeMaxDynamicSharedMemorySize, smem1);
    stage1_kernel<<<BATCH * CH, 384, smem1>>>(skip, dec, wfea, s1, s2, mixw);

    int smem2 = NSTAGE * STAGE_FLOATS * (int)sizeof(float);  // 125440 B
    cudaFuncSetAttribute(mixer_gemm, cudaFuncAttributeMaxDynamicSharedMemorySize, smem2);
    dim3 g2(PIX / GN, BATCH, 1);
    mixer_gemm<<<g2, 512, smem2>>>(skip, out);
}

// round 11
// speedup vs baseline: 1.2965x; 1.0118x over previous
#include <cuda_runtime.h>
#include <cstdint>
#include <math.h>

#define BATCH 16
#define CH    256
#define HW    96
#define PIX   (HW*HW)   // 9216
#define PSTR  104       // padded row stride for sy (98 rows x 104), col offset 4

// scratch: z (tf32-rounded fp32 bits) + fragment-order tf32 weights
__device__ float g_z[(size_t)BATCH * CH * PIX];
__device__ float g_Asw[CH * CH];   // mma-fragment-ordered tf32(W)

__device__ __forceinline__ uint32_t f2tf32(float x) {
    uint32_t r;
    asm("cvt.rna.tf32.f32 %0, %1;" : "=r"(r) : "f"(x));
    return r;
}

// ---------------------------------------------------------------------------
// Stage 1: z = 3y + w_fea*w_edge + DoG(y),  y = skip + dec   (one CTA / plane)
// 384 threads: thread = (r = tid/96 in 0..3, j = tid%96); rows i = 4*it + r.
// y-direction bilinear weights are per-thread constants (row step 4 -> integer
// source steps 1/2/3), so the inner loop uses integer index progressions only.
// ---------------------------------------------------------------------------
__global__ void __launch_bounds__(384) stage1_kernel(
    const float* __restrict__ skip, const float* __restrict__ dec,
    const float* __restrict__ w_fea, const float* __restrict__ s1raw,
    const float* __restrict__ s2raw, const float* __restrict__ W)
{
    extern __shared__ float sm[];
    float* syp = sm;                  // 98*104 = 10192
    float* d0  = syp + 10192;         // 24*24  = 576
    float* d1  = d0 + 576;            // 48*48  = 2304
    float* d2  = d1 + 2304;           // 72*72  = 5184   total 18256 floats

    int plane = blockIdx.x;
    int c = plane & (CH - 1);
    const float* sp = skip + (size_t)plane * PIX;
    const float* dp = dec  + (size_t)plane * PIX;
    float* zp = g_z + (size_t)plane * PIX;
    int tid = threadIdx.x;

    // fold-in: weight fragment swizzle (independent of the rest)
    if (blockIdx.x < 256 && tid < 256) {
        int o = blockIdx.x * 256 + tid;
        int q    = o & 3;
        int lane = (o >> 2) & 31;
        int t    = (o >> 7) & 1;
        int wm   = (o >> 8) & 7;
        int kk   = (o >> 11) & 1;
        int kt   = o >> 12;
        int g = lane >> 2, tig = lane & 3;
        int co = wm * 32 + t * 16 + g + (q & 1) * 8;
        int ci = kt * 16 + kk * 8 + tig + (q >> 1) * 4;
        g_Asw[o] = __uint_as_float(f2tf32(W[co * 256 + ci]));
    }

    // zero border of padded plane
    for (int x = tid; x < PSTR; x += 384) { syp[x] = 0.0f; syp[97 * PSTR + x] = 0.0f; }
    for (int r = tid; r < 98; r += 384)   { syp[r * PSTR + 3] = 0.0f; syp[r * PSTR + 100] = 0.0f; }
    __syncthreads();

    // y = skip + dec, float4 load + aligned float4 padded store
    {
        const float4* s4 = (const float4*)sp;
        const float4* d4 = (const float4*)dp;
        for (int q = tid; q < PIX / 4; q += 384) {
            float4 a = s4[q], b = d4[q];
            int i = q / 24;
            int j4 = (q - i * 24) * 4;
            float4 v = make_float4(a.x + b.x, a.y + b.y, a.z + b.z, a.w + b.w);
            *(float4*)(syp + (i + 1) * PSTR + 4 + j4) = v;
        }
    }
    __syncthreads();

#define SY(i, j) syp[((i) + 1) * PSTR + ((j) + 4)]
    for (int e = tid; e < 24 * 24; e += 384) {
        int oi = e / 24, oj = e % 24;
        d0[e] = 0.25f * (SY(4 * oi + 1, 4 * oj + 1) + SY(4 * oi + 1, 4 * oj + 2) +
                         SY(4 * oi + 2, 4 * oj + 1) + SY(4 * oi + 2, 4 * oj + 2));
    }
    for (int e = tid; e < 48 * 48; e += 384) {
        int oi = e / 48, oj = e % 48;
        d1[e] = 0.25f * (SY(2 * oi, 2 * oj) + SY(2 * oi, 2 * oj + 1) +
                         SY(2 * oi + 1, 2 * oj) + SY(2 * oi + 1, 2 * oj + 1));
    }
    for (int e = tid; e < 72 * 72; e += 384) {
        int oi = e / 72, oj = e % 72;
        float fy = fmaf((float)oi, 96.0f / 72.0f, 96.0f / 144.0f - 0.5f);
        float fx = fmaf((float)oj, 96.0f / 72.0f, 96.0f / 144.0f - 0.5f);
        int y0 = (int)floorf(fy); float wy = fy - (float)y0;
        int x0 = (int)floorf(fx); float wx = fx - (float)x0;
        const float* r0 = &SY(y0, x0);
        float v00 = r0[0], v01 = r0[1], v10 = r0[PSTR], v11 = r0[PSTR + 1];
        float h0 = fmaf(wx, v01 - v00, v00);
        float h1 = fmaf(wx, v11 - v10, v10);
        d2[e] = fmaf(wy, h1 - h0, h0);
    }
    __syncthreads();

    // per-channel DoG kernel coefficients
    float sg1 = 2.0f / (1.0f + expf(-s1raw[c]));
    float sg2 = 2.0f / (1.0f + expf(-s2raw[c]));
    float a1 = expf(-0.5f / (sg1 * sg1)), a2 = a1 * a1;
    float b1 = expf(-0.5f / (sg2 * sg2)), b2 = b1 * b1;
    float in1 = 1.0f / (1.0f + 4.0f * a1 + 4.0f * a2);
    float in2 = 1.0f / (1.0f + 4.0f * b1 + 4.0f * b2);
    float kc3 = 3.0f + in1 - in2;
    float ke = a1 * in1 - b1 * in2;
    float kq = a2 * in1 - b2 * in2;
    float wf = w_fea[c];

    int r = tid / 96;
    int j = tid - r * 96;

    // x-direction bilinear setup (fixed column j)
    float fx0 = 0.25f * j - 0.375f;
    int xi0 = (int)floorf(fx0); float wx0 = fx0 - (float)xi0;
    int x0a = max(xi0, 0), x0b = min(xi0 + 1, 23);
    float fx1 = 0.5f * j - 0.25f;
    int xi1 = (int)floorf(fx1); float wx1 = fx1 - (float)xi1;
    int x1a = max(xi1, 0), x1b = min(xi1 + 1, 47);
    float fx2 = 0.75f * j - 0.125f;
    int xi2 = (int)floorf(fx2); float wx2 = fx2 - (float)xi2;
    int x2a = max(xi2, 0), x2b = min(xi2 + 1, 71);

    // y-direction: constant weights, integer index progressions (steps 1/2/3)
    float fr;
    fr = 0.25f * r - 0.375f; int yb0 = (int)floorf(fr); float wy0 = fr - (float)yb0;
    fr = 0.50f * r - 0.250f; int yb1 = (int)floorf(fr); float wy1 = fr - (float)yb1;
    fr = 0.75f * r - 0.125f; int yb2 = (int)floorf(fr); float wy2 = fr - (float)yb2;

    const float* pc = syp + (r + 1) * PSTR + (j + 4);
    float* zrow = zp + r * 96 + j;

#pragma unroll 4
    for (int it = 0; it < 24; ++it) {
        int y0 = it + yb0;
        const float* p0a = d0 + max(y0, 0) * 24;
        const float* p0b = d0 + min(y0 + 1, 23) * 24;
        float u0;
        { float v00 = p0a[x0a], v01 = p0a[x0b], v10 = p0b[x0a], v11 = p0b[x0b];
          float h0 = fmaf(wx0, v01 - v00, v00);
          float h1 = fmaf(wx0, v11 - v10, v10);
          u0 = fmaf(wy0, h1 - h0, h0); }

        int y1 = 2 * it + yb1;
        const float* p1a = d1 + max(y1, 0) * 48;
        const float* p1b = d1 + min(y1 + 1, 47) * 48;
        float u1;
        { float v00 = p1a[x1a], v01 = p1a[x1b], v10 = p1b[x1a], v11 = p1b[x1b];
          float h0 = fmaf(wx1, v01 - v00, v00);
          float h1 = fmaf(wx1, v11 - v10, v10);
          u1 = fmaf(wy1, h1 - h0, h0); }

        int y2 = 3 * it + yb2;
        const float* p2a = d2 + max(y2, 0) * 72;
        const float* p2b = d2 + min(y2 + 1, 71) * 72;
        float u2;
        { float v00 = p2a[x2a], v01 = p2a[x2b], v10 = p2b[x2a], v11 = p2b[x2b];
          float h0 = fmaf(wx2, v01 - v00, v00);
          float h1 = fmaf(wx2, v11 - v10, v10);
          u2 = fmaf(wy2, h1 - h0, h0); }

        float yv = pc[0];
        float se = pc[-1] + pc[1] + pc[-PSTR] + pc[PSTR];
        float sq = pc[-PSTR - 1] + pc[-PSTR + 1] + pc[PSTR - 1] + pc[PSTR + 1];

        float e0 = fabsf(yv - u0), e1 = fabsf(yv - u1), e2 = fabsf(yv - u2);
        float we = (fabsf(e0 - e1) + fabsf(e0 - e2) + fabsf(e1 - e2)) * (1.0f / 3.0f);
        float z = kc3 * yv + wf * we + ke * se + kq * sq;
        *zrow = __uint_as_float(f2tf32(z));

        pc += 4 * PSTR;
        zrow += 4 * 96;
    }
#undef SY
}

// ---------------------------------------------------------------------------
// Stage 2: out[b,co,p] = sum_ci W[co,ci]*z[b,ci,p] + skip[b,co,p]
// tf32 mma. 256 threads, block tile 128(co) x 128(p), BK=16, 4-stage cp.async
// pipeline, ONE barrier per k-tile, 2 CTAs/SM.
// ---------------------------------------------------------------------------
#define GN 128
#define GK 16
#define BST 136
#define NSTAGE 4
#define A_FLOATS 2048             // 16k x 128m in fragment order
#define B_FLOATS (GK * BST)       // 2176
#define STAGE_FLOATS (A_FLOATS + B_FLOATS)

__device__ __forceinline__ void cp_async16(uint32_t saddr, const void* gptr) {
    asm volatile("cp.async.ca.shared.global [%0], [%1], 16;\n" :: "r"(saddr), "l"(gptr));
}
__device__ __forceinline__ void cp_commit() {
    asm volatile("cp.async.commit_group;\n");
}
template <int N>
__device__ __forceinline__ void cp_wait() {
    asm volatile("cp.async.wait_group %0;\n" :: "n"(N));
}
__device__ __forceinline__ void mma_tf32(float* c, const uint32_t* a, const uint32_t* b) {
    asm volatile(
        "mma.sync.aligned.m16n8k8.row.col.f32.tf32.tf32.f32 "
        "{%0,%1,%2,%3}, {%4,%5,%6,%7}, {%8,%9}, {%0,%1,%2,%3};\n"
        : "+f"(c[0]), "+f"(c[1]), "+f"(c[2]), "+f"(c[3])
        : "r"(a[0]), "r"(a[1]), "r"(a[2]), "r"(a[3]), "r"(b[0]), "r"(b[1]));
}

__global__ void __launch_bounds__(256, 2) mixer_gemm(
    const float* __restrict__ skip, float* __restrict__ out)
{
    extern __shared__ float sm2[];

    int pt = blockIdx.x * GN;
    int chalf = blockIdx.y;                   // 0 or 1: which 128-row co slice
    int b  = blockIdx.z;
    const float* Zb = g_z + (size_t)b * CH * PIX;

    int tid  = threadIdx.x;
    int warp = tid >> 5, lane = tid & 31;
    int wm = warp >> 1, wn = warp & 1;        // 4x2 warps, warp tile 32x64
    int g = lane >> 2, tig = lane & 3;

    // A cp.async mapping: per kt, 2048 floats; this CTA's slice within g_Asw:
    // kt*4096 + kk*2048 + chalf*1024 + rem   (smem: kk*1024 + rem)
    int aoff = tid * 8;                       // 0..2047, two 16B chunks
    int akk  = aoff >> 10;
    int arem = aoff & 1023;
    int asrc_off = akk * 2048 + chalf * 1024 + arem;   // + kt*4096

    // B cp.async mapping: rows of 128 payload floats, stride BST in smem
    int brow = tid >> 4;
    int bcol = (tid & 15) * 8;
    uint32_t bdst_off = brow * BST + bcol;    // two 16B chunks at +0, +4

    float acc[2][8][4];
#pragma unroll
    for (int t = 0; t < 2; t++)
#pragma unroll
        for (int s = 0; s < 8; s++)
#pragma unroll
            for (int q = 0; q < 4; q++) acc[t][s][q] = 0.0f;

    // prologue: stages 0..NSTAGE-2
#pragma unroll
    for (int st = 0; st < NSTAGE - 1; ++st) {
        float* base = sm2 + st * STAGE_FLOATS;
        const float* asrc = g_Asw + st * 4096 + asrc_off;
        cp_async16((uint32_t)__cvta_generic_to_shared(base + aoff), asrc);
        cp_async16((uint32_t)__cvta_generic_to_shared(base + aoff + 4), asrc + 4);
        const float* bsrc = Zb + (size_t)(st * GK + brow) * PIX + pt + bcol;
        float* bb = base + A_FLOATS;
        cp_async16((uint32_t)__cvta_generic_to_shared(bb + bdst_off), bsrc);
        cp_async16((uint32_t)__cvta_generic_to_shared(bb + bdst_off + 4), bsrc + 4);
        cp_commit();
    }

    for (int kt = 0; kt < 16; ++kt) {
        cp_wait<NSTAGE - 2>();
        __syncthreads();

        int nk = kt + NSTAGE - 1;
        if (nk < 16) {
            float* base = sm2 + (nk & (NSTAGE - 1)) * STAGE_FLOATS;
            const float* asrc = g_Asw + nk * 4096 + asrc_off;
            cp_async16((uint32_t)__cvta_generic_to_shared(base + aoff), asrc);
            cp_async16((uint32_t)__cvta_generic_to_shared(base + aoff + 4), asrc + 4);
            const float* bsrc = Zb + (size_t)(nk * GK + brow) * PIX + pt + bcol;
            float* bb = base + A_FLOATS;
            cp_async16((uint32_t)__cvta_generic_to_shared(bb + bdst_off), bsrc);
            cp_async16((uint32_t)__cvta_generic_to_shared(bb + bdst_off + 4), bsrc + 4);
        }
        cp_commit();

        const float* as_s = sm2 + (kt & (NSTAGE - 1)) * STAGE_FLOATS;
        const float* bs_s = as_s + A_FLOATS;
#pragma unroll
        for (int kk = 0; kk < 2; kk++) {
            // A fragments: one LDS.128 per t (lane-contiguous, conflict-free)
            uint4 a0 = *(const uint4*)(as_s + kk * 1024 + wm * 256 + lane * 4);
            uint4 a1 = *(const uint4*)(as_s + kk * 1024 + wm * 256 + 128 + lane * 4);
            const uint32_t* br0 = (const uint32_t*)(bs_s + (kk * 8 + tig) * BST);
            const uint32_t* br1 = (const uint32_t*)(bs_s + (kk * 8 + tig + 4) * BST);
            uint32_t bf[8][2];
#pragma unroll
            for (int s = 0; s < 8; s++) {
                int cn = wn * 64 + s * 8 + g;
                bf[s][0] = br0[cn];
                bf[s][1] = br1[cn];
            }
#pragma unroll
            for (int s = 0; s < 8; s++) {
                mma_tf32(acc[0][s], &a0.x, bf[s]);
                mma_tf32(acc[1][s], &a1.x, bf[s]);
            }
        }
        // no trailing barrier: the next iteration's top barrier orders the
        // overwrite of this stage (cp target of kt+1 == compute stage of kt)
    }

    // epilogue: + skip, write out
#pragma unroll
    for (int t = 0; t < 2; t++) {
        int row = chalf * 128 + wm * 32 + t * 16 + g;
#pragma unroll
        for (int s = 0; s < 8; s++) {
            int col = pt + wn * 64 + s * 8 + tig * 2;
            size_t base0 = ((size_t)b * CH + row) * PIX + col;
            size_t base1 = base0 + (size_t)8 * PIX;
            float2 k0 = *(const float2*)(skip + base0);
            float2 k1 = *(const float2*)(skip + base1);
            float2 o0 = make_float2(acc[t][s][0] + k0.x, acc[t][s][1] + k0.y);
            float2 o1 = make_float2(acc[t][s][2] + k1.x, acc[t][s][3] + k1.y);
            *(float2*)(out + base0) = o0;
            *(float2*)(out + base1) = o1;
        }
    }
}

// ---------------------------------------------------------------------------
extern "C" void kernel_launch(void* const* d_in, const int* in_sizes, int n_in,
                              void* d_out, int out_size) {
    const float* skip = (const float*)d_in[0];
    const float* dec  = (const float*)d_in[1];
    const float* wfea = (const float*)d_in[2];
    const float* s1   = (const float*)d_in[3];
    const float* s2   = (const float*)d_in[4];
    const float* mixw = (const float*)d_in[5];
    float* out = (float*)d_out;

    int smem1 = 18256 * (int)sizeof(float);   // 73024 B
    cudaFuncSetAttribute(stage1_kernel, cudaFuncAttributeMaxDynamicSharedMemorySize, smem1);
    stage1_kernel<<<BATCH * CH, 384, smem1>>>(skip, dec, wfea, s1, s2, mixw);

    int smem2 = NSTAGE * STAGE_FLOATS * (int)sizeof(float);  // 67584 B
    cudaFuncSetAttribute(mixer_gemm, cudaFuncAttributeMaxDynamicSharedMemorySize, smem2);
    dim3 g2(PIX / GN, 2, BATCH);
    mixer_gemm<<<g2, 256, smem2>>>(skip, out);
}

// round 15
// speedup vs baseline: 1.3335x; 1.0286x over previous
#include <cuda_runtime.h>
#include <cstdint>
#include <math.h>

#define BATCH 16
#define CH    256
#define HW    96
#define PIX   (HW*HW)   // 9216
#define PSTR  104       // padded row stride for sy (98 rows x 104), col offset 4

// scratch: z (tf32-rounded fp32 bits) + fragment-order tf32 weights
__device__ float g_z[(size_t)BATCH * CH * PIX];
// layout: [kt16][chalf2][kk2][wm4][t2][lane32][q4]  -> per (kt,chalf) 2048 floats contiguous
__device__ float g_Asw[CH * CH];

__device__ __forceinline__ uint32_t f2tf32(float x) {
    uint32_t r;
    asm("cvt.rna.tf32.f32 %0, %1;" : "=r"(r) : "f"(x));
    return r;
}

// ---------------------------------------------------------------------------
// Stage 1: z = 3y + w_fea*w_edge + DoG(y),  y = skip + dec   (one CTA / plane)
// ---------------------------------------------------------------------------
__global__ void __launch_bounds__(384) stage1_kernel(
    const float* __restrict__ skip, const float* __restrict__ dec,
    const float* __restrict__ w_fea, const float* __restrict__ s1raw,
    const float* __restrict__ s2raw, const float* __restrict__ W)
{
    extern __shared__ float sm[];
    float* syp = sm;                  // 98*104 = 10192
    float* d0  = syp + 10192;         // 24*24  = 576
    float* d1  = d0 + 576;            // 48*48  = 2304
    float* d2  = d1 + 2304;           // 72*72  = 5184   total 18256 floats

    int plane = blockIdx.x;
    int c = plane & (CH - 1);
    const float* sp = skip + (size_t)plane * PIX;
    const float* dp = dec  + (size_t)plane * PIX;
    float* zp = g_z + (size_t)plane * PIX;
    int tid = threadIdx.x;

    // fold-in: weight fragment swizzle for the GEMM's bulk-copy layout
    if (blockIdx.x < 256 && tid < 256) {
        int o = blockIdx.x * 256 + tid;
        int q     = o & 3;
        int lane  = (o >> 2) & 31;
        int t     = (o >> 7) & 1;
        int wm4   = (o >> 8) & 3;
        int kk    = (o >> 10) & 1;
        int chalf = (o >> 11) & 1;
        int kt    = o >> 12;
        int g = lane >> 2, tig = lane & 3;
        int co = chalf * 128 + wm4 * 32 + t * 16 + g + (q & 1) * 8;
        int ci = kt * 16 + kk * 8 + tig + (q >> 1) * 4;
        g_Asw[o] = __uint_as_float(f2tf32(W[co * 256 + ci]));
    }

    // border zero + interior fill (disjoint writes -> single phase)
    for (int x = tid; x < PSTR; x += 384) { syp[x] = 0.0f; syp[97 * PSTR + x] = 0.0f; }
    for (int r = tid; r < 98; r += 384)   { syp[r * PSTR + 3] = 0.0f; syp[r * PSTR + 100] = 0.0f; }
    {
        const float4* s4 = (const float4*)sp;
        const float4* d4 = (const float4*)dp;
        for (int q = tid; q < PIX / 4; q += 384) {
            float4 a = s4[q], b = d4[q];
            int i = q / 24;
            int j4 = (q - i * 24) * 4;
            float4 v = make_float4(a.x + b.x, a.y + b.y, a.z + b.z, a.w + b.w);
            *(float4*)(syp + (i + 1) * PSTR + 4 + j4) = v;
        }
    }
    __syncthreads();

#define SY(i, j) syp[((i) + 1) * PSTR + ((j) + 4)]
    for (int e = tid; e < 24 * 24; e += 384) {
        int oi = e / 24, oj = e % 24;
        d0[e] = 0.25f * (SY(4 * oi + 1, 4 * oj + 1) + SY(4 * oi + 1, 4 * oj + 2) +
                         SY(4 * oi + 2, 4 * oj + 1) + SY(4 * oi + 2, 4 * oj + 2));
    }
    for (int e = tid; e < 48 * 48; e += 384) {
        int oi = e / 48, oj = e % 48;
        d1[e] = 0.25f * (SY(2 * oi, 2 * oj) + SY(2 * oi, 2 * oj + 1) +
                         SY(2 * oi + 1, 2 * oj) + SY(2 * oi + 1, 2 * oj + 1));
    }
    for (int e = tid; e < 72 * 72; e += 384) {
        int oi = e / 72, oj = e % 72;
        float fy = fmaf((float)oi, 96.0f / 72.0f, 96.0f / 144.0f - 0.5f);
        float fx = fmaf((float)oj, 96.0f / 72.0f, 96.0f / 144.0f - 0.5f);
        int y0 = (int)floorf(fy); float wy = fy - (float)y0;
        int x0 = (int)floorf(fx); float wx = fx - (float)x0;
        const float* r0 = &SY(y0, x0);
        float v00 = r0[0], v01 = r0[1], v10 = r0[PSTR], v11 = r0[PSTR + 1];
        float h0 = fmaf(wx, v01 - v00, v00);
        float h1 = fmaf(wx, v11 - v10, v10);
        d2[e] = fmaf(wy, h1 - h0, h0);
    }
    __syncthreads();

    // per-channel DoG kernel coefficients
    float sg1 = 2.0f / (1.0f + expf(-s1raw[c]));
    float sg2 = 2.0f / (1.0f + expf(-s2raw[c]));
    float a1 = expf(-0.5f / (sg1 * sg1)), a2 = a1 * a1;
    float b1 = expf(-0.5f / (sg2 * sg2)), b2 = b1 * b1;
    float in1 = 1.0f / (1.0f + 4.0f * a1 + 4.0f * a2);
    float in2 = 1.0f / (1.0f + 4.0f * b1 + 4.0f * b2);
    float kc3 = 3.0f + in1 - in2;
    float ke = a1 * in1 - b1 * in2;
    float kq = a2 * in1 - b2 * in2;
    float wf = w_fea[c];

    int r = tid / 96;
    int j = tid - r * 96;

    // x-direction bilinear setup (fixed column j)
    float fx0 = 0.25f * j - 0.375f;
    int xi0 = (int)floorf(fx0); float wx0 = fx0 - (float)xi0;
    int x0a = max(xi0, 0), x0b = min(xi0 + 1, 23);
    float fx1 = 0.5f * j - 0.25f;
    int xi1 = (int)floorf(fx1); float wx1 = fx1 - (float)xi1;
    int x1a = max(xi1, 0), x1b = min(xi1 + 1, 47);
    float fx2 = 0.75f * j - 0.125f;
    int xi2 = (int)floorf(fx2); float wx2 = fx2 - (float)xi2;
    int x2a = max(xi2, 0), x2b = min(xi2 + 1, 71);

    // y-direction: constant weights, integer index progressions (steps 1/2/3)
    float fr;
    fr = 0.25f * r - 0.375f; int yb0 = (int)floorf(fr); float wy0 = fr - (float)yb0;
    fr = 0.50f * r - 0.250f; int yb1 = (int)floorf(fr); float wy1 = fr - (float)yb1;
    fr = 0.75f * r - 0.125f; int yb2 = (int)floorf(fr); float wy2 = fr - (float)yb2;

    const float* pc = syp + (r + 1) * PSTR + (j + 4);
    float* zrow = zp + r * 96 + j;

#pragma unroll 4
    for (int it = 0; it < 24; ++it) {
        int y0 = it + yb0;
        const float* p0a = d0 + max(y0, 0) * 24;
        const float* p0b = d0 + min(y0 + 1, 23) * 24;
        float u0;
        { float v00 = p0a[x0a], v01 = p0a[x0b], v10 = p0b[x0a], v11 = p0b[x0b];
          float h0 = fmaf(wx0, v01 - v00, v00);
          float h1 = fmaf(wx0, v11 - v10, v10);
          u0 = fmaf(wy0, h1 - h0, h0); }

        int y1 = 2 * it + yb1;
        const float* p1a = d1 + max(y1, 0) * 48;
        const float* p1b = d1 + min(y1 + 1, 47) * 48;
        float u1;
        { float v00 = p1a[x1a], v01 = p1a[x1b], v10 = p1b[x1a], v11 = p1b[x1b];
          float h0 = fmaf(wx1, v01 - v00, v00);
          float h1 = fmaf(wx1, v11 - v10, v10);
          u1 = fmaf(wy1, h1 - h0, h0); }

        int y2 = 3 * it + yb2;
        const float* p2a = d2 + max(y2, 0) * 72;
        const float* p2b = d2 + min(y2 + 1, 71) * 72;
        float u2;
        { float v00 = p2a[x2a], v01 = p2a[x2b], v10 = p2b[x2a], v11 = p2b[x2b];
          float h0 = fmaf(wx2, v01 - v00, v00);
          float h1 = fmaf(wx2, v11 - v10, v10);
          u2 = fmaf(wy2, h1 - h0, h0); }

        float yv = pc[0];
        float se = pc[-1] + pc[1] + pc[-PSTR] + pc[PSTR];
        float sq = pc[-PSTR - 1] + pc[-PSTR + 1] + pc[PSTR - 1] + pc[PSTR + 1];

        float e0 = fabsf(yv - u0), e1 = fabsf(yv - u1), e2 = fabsf(yv - u2);
        float we = (fabsf(e0 - e1) + fabsf(e0 - e2) + fabsf(e1 - e2)) * (1.0f / 3.0f);
        float z = kc3 * yv + wf * we + ke * se + kq * sq;
        *zrow = __uint_as_float(f2tf32(z));

        pc += 4 * PSTR;
        zrow += 4 * 96;
    }
#undef SY
}

// ---------------------------------------------------------------------------
// Stage 2: out[b,co,p] = sum_ci W[co,ci]*z[b,ci,p] + skip[b,co,p]
// tf32 mma. 256 threads, tile 128(co) x 128(p), BK=16, 4-stage pipeline fed by
// cp.async.bulk (TMA path) from ONE elected thread + mbarrier full/empty pairs.
// No per-thread LSU fill traffic, no __syncthreads in the main loop. 2 CTAs/SM.
// ---------------------------------------------------------------------------
#define GN 128
#define GK 16
#define BST 136
#define NSTAGE 4
#define A_FLOATS 2048
#define B_FLOATS (GK * BST)              // 2176
#define STAGE_FLOATS (A_FLOATS + B_FLOATS)   // 4224 floats = 16896 B
#define STAGE_BYTES (STAGE_FLOATS * 4)
#define TX_BYTES (A_FLOATS * 4 + GK * GN * 4) // 8192 + 8192 = 16384
#define MBAR_RESERVE 64                  // floats (256 B) for barriers

__device__ __forceinline__ void mbar_init(uint32_t mbar, uint32_t count) {
    asm volatile("mbarrier.init.shared.b64 [%0], %1;" :: "r"(mbar), "r"(count) : "memory");
}
__device__ __forceinline__ void mbar_expect_tx(uint32_t mbar, uint32_t bytes) {
    asm volatile("mbarrier.arrive.expect_tx.shared.b64 _, [%0], %1;" :: "r"(mbar), "r"(bytes) : "memory");
}
__device__ __forceinline__ void mbar_arrive(uint32_t mbar) {
    asm volatile("mbarrier.arrive.shared.b64 _, [%0];" :: "r"(mbar) : "memory");
}
__device__ __forceinline__ void mbar_wait(uint32_t mbar, uint32_t parity) {
    asm volatile(
        "{\n\t.reg .pred P;\n\t"
        "WAIT_%=:\n\t"
        "mbarrier.try_wait.parity.acquire.cta.shared::cta.b64 P, [%0], %1, 0x989680;\n\t"
        "@P bra.uni DONE_%=;\n\t"
        "bra.uni WAIT_%=;\n\t"
        "DONE_%=:\n\t}"
        :: "r"(mbar), "r"(parity) : "memory");
}
__device__ __forceinline__ void bulk_g2s(uint32_t dst, const void* src, uint32_t bytes, uint32_t mbar) {
    asm volatile(
        "cp.async.bulk.shared::cluster.global.mbarrier::complete_tx::bytes [%0], [%1], %2, [%3];"
        :: "r"(dst), "l"(src), "r"(bytes), "r"(mbar) : "memory");
}
__device__ __forceinline__ void mma_tf32(float* c, const uint32_t* a, const uint32_t* b) {
    asm volatile(
        "mma.sync.aligned.m16n8k8.row.col.f32.tf32.tf32.f32 "
        "{%0,%1,%2,%3}, {%4,%5,%6,%7}, {%8,%9}, {%0,%1,%2,%3};\n"
        : "+f"(c[0]), "+f"(c[1]), "+f"(c[2]), "+f"(c[3])
        : "r"(a[0]), "r"(a[1]), "r"(a[2]), "r"(a[3]), "r"(b[0]), "r"(b[1]));
}

// fill stage (f & 3) with k-tile f: A 8KB (contiguous) + 16 B-rows of 512B
__device__ __forceinline__ void fill_stage(uint32_t smem_u32, int f, int chalf,
                                           const float* Zb, int pt) {
    int stage = f & 3;
    uint32_t full = smem_u32 + stage * 16;
    uint32_t dbase = smem_u32 + MBAR_RESERVE * 4 + stage * STAGE_BYTES;
    mbar_expect_tx(full, TX_BYTES);
    bulk_g2s(dbase, g_Asw + f * 4096 + chalf * 2048, 8192, full);
    const float* bs = Zb + (size_t)(f * 16) * PIX + pt;
#pragma unroll
    for (int r = 0; r < 16; r++)
        bulk_g2s(dbase + 8192 + r * (BST * 4), bs + (size_t)r * PIX, 512, full);
}

__global__ void __launch_bounds__(256, 2) mixer_gemm(
    const float* __restrict__ skip, float* __restrict__ out)
{
    extern __shared__ float sm2[];
    uint32_t smem_u32;
    asm("{ .reg .u64 t; cvta.to.shared.u64 t, %1; cvt.u32.u64 %0, t; }"
        : "=r"(smem_u32) : "l"(sm2));
    float* data0 = sm2 + MBAR_RESERVE;

    int pt = blockIdx.x * GN;
    int chalf = blockIdx.y;
    int b  = blockIdx.z;
    const float* Zb = g_z + (size_t)b * CH * PIX;

    int tid  = threadIdx.x;
    int warp = tid >> 5, lane = tid & 31;
    int wm = warp >> 1, wn = warp & 1;        // 4x2 warps, warp tile 32x64
    int g = lane >> 2, tig = lane & 3;

    // init barriers: full[s] at +s*16 (count 1), empty[s] at +s*16+8 (count 256)
    if (tid == 0) {
        for (int s = 0; s < NSTAGE; s++) {
            mbar_init(smem_u32 + s * 16, 1);
            mbar_init(smem_u32 + s * 16 + 8, 256);
        }
        asm volatile("fence.proxy.async.shared::cta;" ::: "memory");
    }
    __syncthreads();

    // prologue: fill k-tiles 0..2 (fresh stages, no empty wait)
    if (tid == 0) {
#pragma unroll
        for (int f = 0; f < NSTAGE - 1; f++) fill_stage(smem_u32, f, chalf, Zb, pt);
    }

    float acc[2][8][4];
#pragma unroll
    for (int t = 0; t < 2; t++)
#pragma unroll
        for (int s = 0; s < 8; s++)
#pragma unroll
            for (int q = 0; q < 4; q++) acc[t][s][q] = 0.0f;

    int cph = 0;   // consumer full-wait phase
    for (int kt = 0; kt < 16; ++kt) {
        int stage = kt & 3;
        mbar_wait(smem_u32 + stage * 16, cph);

        const float* as_s = data0 + stage * STAGE_FLOATS;
        const float* bs_s = as_s + A_FLOATS;
#pragma unroll
        for (int kk = 0; kk < 2; kk++) {
            uint4 a0 = *(const uint4*)(as_s + kk * 1024 + wm * 256 + lane * 4);
            uint4 a1 = *(const uint4*)(as_s + kk * 1024 + wm * 256 + 128 + lane * 4);
            const uint32_t* br0 = (const uint32_t*)(bs_s + (kk * 8 + tig) * BST);
            const uint32_t* br1 = (const uint32_t*)(bs_s + (kk * 8 + tig + 4) * BST);
            uint32_t bf[8][2];
#pragma unroll
            for (int s = 0; s < 8; s++) {
                int cn = wn * 64 + s * 8 + g;
                bf[s][0] = br0[cn];
                bf[s][1] = br1[cn];
            }
#pragma unroll
            for (int s = 0; s < 8; s++) {
                mma_tf32(acc[0][s], &a0.x, bf[s]);
                mma_tf32(acc[1][s], &a1.x, bf[s]);
            }
        }
        // done with this stage's smem (mma consumed register fragments)
        mbar_arrive(smem_u32 + stage * 16 + 8);

        // producer: refill the stage just released (f = kt + 3)
        if (tid == 0) {
            int f = kt + NSTAGE - 1;
            if (f < 16) {
                mbar_wait(smem_u32 + (f & 3) * 16 + 8, 1 ^ ((f >> 2) & 1));
                fill_stage(smem_u32, f, chalf, Zb, pt);
            }
        }
        if (stage == 3) cph ^= 1;
    }

    // epilogue: + skip, write out
#pragma unroll
    for (int t = 0; t < 2; t++) {
        int row = chalf * 128 + wm * 32 + t * 16 + g;
#pragma unroll
        for (int s = 0; s < 8; s++) {
            int col = pt + wn * 64 + s * 8 + tig * 2;
            size_t base0 = ((size_t)b * CH + row) * PIX + col;
            size_t base1 = base0 + (size_t)8 * PIX;
            float2 k0 = *(const float2*)(skip + base0);
            float2 k1 = *(const float2*)(skip + base1);
            float2 o0 = make_float2(acc[t][s][0] + k0.x, acc[t][s][1] + k0.y);
            float2 o1 = make_float2(acc[t][s][2] + k1.x, acc[t][s][3] + k1.y);
            *(float2*)(out + base0) = o0;
            *(float2*)(out + base1) = o1;
        }
    }
}

// ---------------------------------------------------------------------------
extern "C" void kernel_launch(void* const* d_in, const int* in_sizes, int n_in,
                              void* d_out, int out_size) {
    const float* skip = (const float*)d_in[0];
    const float* dec  = (const float*)d_in[1];
    const float* wfea = (const float*)d_in[2];
    const float* s1   = (const float*)d_in[3];
    const float* s2   = (const float*)d_in[4];
    const float* mixw = (const float*)d_in[5];
    float* out = (float*)d_out;

    int smem1 = 18256 * (int)sizeof(float);   // 73024 B
    cudaFuncSetAttribute(stage1_kernel, cudaFuncAttributeMaxDynamicSharedMemorySize, smem1);
    stage1_kernel<<<BATCH * CH, 384, smem1>>>(skip, dec, wfea, s1, s2, mixw);

    int smem2 = (MBAR_RESERVE + NSTAGE * STAGE_FLOATS) * (int)sizeof(float);  // 67840 B
    cudaFuncSetAttribute(mixer_gemm, cudaFuncAttributeMaxDynamicSharedMemorySize, smem2);
    dim3 g2(PIX / GN, 2, BATCH);
    mixer_gemm<<<g2, 256, smem2>>>(skip, out);
}